// round 13
// baseline (speedup 1.0000x reference)
#include <cuda_runtime.h>
#include <cuda_fp16.h>
#include <cstdint>

#define NN 256
#define NT 2048
#define NF 128

__device__ __half g_adj16[NN * NN];   // rownorm(adj+I), fp16, [m][k]

__device__ __forceinline__ uint32_t smem_u32(const void* p) {
    uint32_t a;
    asm("{ .reg .u64 t; cvta.to.shared.u64 t, %1; cvt.u32.u64 %0, t; }" : "=r"(a) : "l"(p));
    return a;
}
__device__ __forceinline__ uint32_t packh2(float x, float y) {
    __half2 h = __floats2half2_rn(x, y);
    return *reinterpret_cast<uint32_t*>(&h);
}

// ---------------------------------------------------------------------------
__global__ void prep_kernel(const float* __restrict__ adj) {
    __shared__ float red[256];
    int m = blockIdx.x, j = threadIdx.x;
    float v = adj[m * NN + j] + (j == m ? 1.0f : 0.0f);
    red[j] = v;
    __syncthreads();
#pragma unroll
    for (int off = 128; off > 0; off >>= 1) {
        if (j < off) red[j] += red[j + off];
        __syncthreads();
    }
    g_adj16[m * NN + j] = __float2half_rn(v / red[0]);
}

// ---------------------------------------------------------------------------
// Fused GCN, n-split for occupancy: 2 CTAs per t, each does 256 nodes x 64 o.
// 256 threads = 8 warps (4m x 2n), warp tile 64x32, m16n8k16, fp32 accum.
// 2 CTAs/SM (regs capped 128, smem 88 KB/CTA).
//
// smem per CTA (88 KB):
//   SW  [0,     16384): W half fp16, 128 k-rows x 128B, XOR swizzle
//   SXW [16384, 49152): xw half slab fp16, 256 rows x 128B, XOR swizzle
//   STG [49152, 90112): A staging, 2 stages x (256 rows x 80B)
// ---------------------------------------------------------------------------
#define SW_OFF   0
#define SXW_OFF  16384
#define STG_OFF  49152
#define ASTAGE   20480
#define SMEM_TOT 90112

__global__ void __launch_bounds__(256, 2)
fused_gcn(const float* __restrict__ X, const float* __restrict__ W,
          float* __restrict__ out, const float* __restrict__ bias)
{
    extern __shared__ __align__(128) char smem[];
    const uint32_t base = smem_u32(smem);
    const uint32_t SW  = base + SW_OFF;
    const uint32_t SXW = base + SXW_OFF;
    const uint32_t STG = base + STG_OFF;

    const int bid  = blockIdx.x;
    const int t    = bid >> 1;
    const int o0   = (bid & 1) * 64;        // this CTA's o-half
    const int tid  = threadIdx.x;
    const int warp = tid >> 5;
    const int lane = tid & 31;
    const int lr   = lane & 15, lh = lane >> 4;
    const int grp  = lane >> 2, tg = lane & 3;
    const int warp_m = (warp & 3) * 64;     // 4 warps in m
    const int warp_n = (warp >> 2) * 32;    // 2 warps in n (of 64)

    float acc[4][4][4];                     // 64 regs
    float4 xr[2][2];                        // small staging transients (16 regs)

    auto zero_acc = [&] {
#pragma unroll
        for (int i = 0; i < 4; i++)
#pragma unroll
            for (int j = 0; j < 4; j++)
#pragma unroll
                for (int r = 0; r < 4; r++) acc[i][j][r] = 0.0f;
    };
    auto sts16 = [](uint32_t addr, uint4 v) {
        asm volatile("st.shared.v4.b32 [%0], {%1,%2,%3,%4};"
                     :: "r"(addr), "r"(v.x), "r"(v.y), "r"(v.z), "r"(v.w) : "memory");
    };

    // ---- producers: one BK32 chunk = 1024 16B units; 4/thread in 2 waves ----
    auto stageX = [&](int c, int s) {
#pragma unroll
        for (int h = 0; h < 2; h++) {
#pragma unroll
            for (int i = 0; i < 2; i++) {
                int u = tid + (h * 2 + i) * 256;
                int row = u >> 2, seg = u & 3;
                const float4* src = (const float4*)(X + ((size_t)row * NT + t) * NF + c * 32 + seg * 8);
                xr[i][0] = src[0];
                xr[i][1] = src[1];
            }
#pragma unroll
            for (int i = 0; i < 2; i++) {
                int u = tid + (h * 2 + i) * 256;
                int row = u >> 2, seg = u & 3;
                uint4 v;
                v.x = packh2(xr[i][0].x, xr[i][0].y); v.y = packh2(xr[i][0].z, xr[i][0].w);
                v.z = packh2(xr[i][1].x, xr[i][1].y); v.w = packh2(xr[i][1].z, xr[i][1].w);
                sts16(STG + s * ASTAGE + row * 80 + seg * 16, v);
            }
        }
    };
    auto stageAdj = [&](int c, int s) {
#pragma unroll
        for (int h = 0; h < 2; h++) {
            uint4 a0, a1;
            {
                int u0 = tid + (h * 2 + 0) * 256;
                int u1 = tid + (h * 2 + 1) * 256;
                a0 = *(const uint4*)(g_adj16 + (u0 >> 2) * NN + c * 32 + (u0 & 3) * 8);
                a1 = *(const uint4*)(g_adj16 + (u1 >> 2) * NN + c * 32 + (u1 & 3) * 8);
            }
            {
                int u0 = tid + (h * 2 + 0) * 256;
                int u1 = tid + (h * 2 + 1) * 256;
                sts16(STG + s * ASTAGE + (u0 >> 2) * 80 + (u0 & 3) * 16, a0);
                sts16(STG + s * ASTAGE + (u1 >> 2) * 80 + (u1 & 3) * 16, a1);
            }
        }
    };

    // one BK32 chunk of mma: A from staging stage s (80B rows), B from Bbase
    // (128B rows, XOR swizzle)
    auto mma_stage = [&](int c, int s, uint32_t Bbase) {
        const uint32_t ab = STG + s * ASTAGE;
#pragma unroll
        for (int kk = 0; kk < 2; kk++) {
            const int ke = kk * 16;
            uint32_t a[4][4];
#pragma unroll
            for (int fm = 0; fm < 4; fm++) {
                uint32_t ad = ab + (warp_m + fm * 16 + lr) * 80 + lh * 16 + ke * 2;
                asm volatile("ldmatrix.sync.aligned.m8n8.x4.shared.b16 {%0,%1,%2,%3}, [%4];"
                             : "=r"(a[fm][0]), "=r"(a[fm][1]), "=r"(a[fm][2]), "=r"(a[fm][3])
                             : "r"(ad));
            }
            uint32_t b[2][4];
#pragma unroll
            for (int np = 0; np < 2; np++) {
                int krw = c * 32 + ke + lr;
                uint32_t bn = (uint32_t)(warp_n + np * 16 + lh * 8) * 2;   // [0,128) bytes
                uint32_t bd = Bbase + krw * 128 + (bn ^ ((krw & 7) << 4));
                asm volatile("ldmatrix.sync.aligned.m8n8.x4.trans.shared.b16 {%0,%1,%2,%3}, [%4];"
                             : "=r"(b[np][0]), "=r"(b[np][1]), "=r"(b[np][2]), "=r"(b[np][3])
                             : "r"(bd));
            }
#pragma unroll
            for (int fm = 0; fm < 4; fm++)
#pragma unroll
                for (int fn = 0; fn < 4; fn++) {
                    const int np = fn >> 1, pr = fn & 1;
                    asm volatile(
                        "mma.sync.aligned.m16n8k16.row.col.f32.f16.f16.f32 "
                        "{%0,%1,%2,%3}, {%4,%5,%6,%7}, {%8,%9}, {%0,%1,%2,%3};"
                        : "+f"(acc[fm][fn][0]), "+f"(acc[fm][fn][1]),
                          "+f"(acc[fm][fn][2]), "+f"(acc[fm][fn][3])
                        : "r"(a[fm][0]), "r"(a[fm][1]), "r"(a[fm][2]), "r"(a[fm][3]),
                          "r"(b[np][pr * 2]), "r"(b[np][pr * 2 + 1]));
                }
        }
    };

    // ---- prologue: W half -> SW (fp16, 128B rows, XOR), X chunk 0 ----
#pragma unroll
    for (int i = 0; i < 4; i++) {
        int u = tid + i * 256;                 // 1024 units
        int row = u >> 3, seg = u & 7;         // 128 k-rows x 8 segs
        const float4* src = (const float4*)(W + row * NF + o0 + seg * 8);
        float4 v0 = src[0], v1 = src[1];
        uint4 w;
        w.x = packh2(v0.x, v0.y); w.y = packh2(v0.z, v0.w);
        w.z = packh2(v1.x, v1.y); w.w = packh2(v1.z, v1.w);
        sts16(SW + row * 128 + ((seg * 16) ^ ((row & 7) << 4)), w);
    }
    stageX(0, 0);
    zero_acc();
    __syncthreads();

    // ---- phase 1: xw_half = X_t @ W_half (K=128, 4 chunks) ----
#pragma unroll
    for (int c = 0; c < 4; c++) {
        const int s = c & 1;
        mma_stage(c, s, SW);
        if (c < 3) { stageX(c + 1, s ^ 1); __syncthreads(); }
    }

    // phase-1 epilogue: acc -> SXW (fp16, 128B rows, XOR)
#pragma unroll
    for (int fm = 0; fm < 4; fm++) {
        const int r0 = warp_m + fm * 16 + grp;
#pragma unroll
        for (int fn = 0; fn < 4; fn++) {
            const int cb = (warp_n + fn * 8 + tg * 2) * 2;    // [0,128) bytes
            uint32_t h0 = packh2(acc[fm][fn][0], acc[fm][fn][1]);
            uint32_t h1 = packh2(acc[fm][fn][2], acc[fm][fn][3]);
            asm volatile("st.shared.b32 [%0], %1;"
                         :: "r"(SXW + r0 * 128 + (cb ^ ((r0 & 7) << 4))), "r"(h0) : "memory");
            asm volatile("st.shared.b32 [%0], %1;"
                         :: "r"(SXW + (r0 + 8) * 128 + (cb ^ (((r0 + 8) & 7) << 4))), "r"(h1) : "memory");
        }
    }
    zero_acc();

    // ---- phase 2: out_half = adj_hat @ xw_half + bias (K=256, 8 chunks) ----
    stageAdj(0, 0);
    __syncthreads();
#pragma unroll
    for (int c = 0; c < 8; c++) {
        const int s = c & 1;
        mma_stage(c, s, SXW);
        if (c < 7) { stageAdj(c + 1, s ^ 1); __syncthreads(); }
    }

    // phase-2 epilogue
#pragma unroll
    for (int fm = 0; fm < 4; fm++) {
        const int r0 = warp_m + fm * 16 + grp;
#pragma unroll
        for (int fn = 0; fn < 4; fn++) {
            const int col = o0 + warp_n + fn * 8 + tg * 2;
            float2 b2 = *(const float2*)(bias + col);
            float2 v0 = { acc[fm][fn][0] + b2.x, acc[fm][fn][1] + b2.y };
            float2 v1 = { acc[fm][fn][2] + b2.x, acc[fm][fn][3] + b2.y };
            *(float2*)(out + ((size_t)r0 * NT + t) * NF + col)       = v0;
            *(float2*)(out + ((size_t)(r0 + 8) * NT + t) * NF + col) = v1;
        }
    }
}

// ---------------------------------------------------------------------------
extern "C" void kernel_launch(void* const* d_in, const int* in_sizes, int n_in,
                              void* d_out, int out_size) {
    (void)in_sizes; (void)n_in; (void)out_size;
    const float* node_feats = (const float*)d_in[0];   // [256,2048,128]
    const float* adj        = (const float*)d_in[1];   // [256,256]
    const float* weight     = (const float*)d_in[2];   // [128,128]
    const float* bias       = (const float*)d_in[3];   // [128]
    float* out = (float*)d_out;

    cudaFuncSetAttribute(fused_gcn, cudaFuncAttributeMaxDynamicSharedMemorySize, SMEM_TOT);

    prep_kernel<<<NN, 256>>>(adj);
    fused_gcn<<<2 * NT, 256, SMEM_TOT>>>(node_feats, weight, out, bias);
}